// round 11
// baseline (speedup 1.0000x reference)
#include <cuda_runtime.h>
#include <cuda_fp16.h>
#include <cstdint>

// Problem constants
#define Bb   2
#define Ss   2048
#define HID  1024
#define NH   16
#define NKV  8
#define HD   128
#define MROWS (Bb*Ss)          // 4096
#define QDIM (NH*HD)           // 2048
#define KDIM (NKV*HD)          // 1024
#define NQKV (QDIM + 2*KDIM)   // 4096 combined
#define SCALE 0.08838834764831845f

// ---------------------------------------------------------------------------
// Scratch (static device memory; no allocation APIs)
// ---------------------------------------------------------------------------
__device__ __half g_qTh[(size_t)Bb * NH * Ss * HD];    // [b][h][s][d]
__device__ __half g_kTh[(size_t)Bb * NKV * Ss * HD];   // [b][hk][s][d]
__device__ __half g_vTh[(size_t)Bb * NKV * Ss * HD];   // [b][hk][d][s] transposed
__device__ __half g_attnH[(size_t)MROWS * QDIM];       // flash output (half)
__device__ __half g_xH[(size_t)MROWS * HID];
__device__ __half g_wqkvH[(size_t)NQKV * HID];         // [Wq;Wk;Wv] rows
__device__ __half g_woH[(size_t)HID * QDIM];

__device__ __forceinline__ uint32_t s2u(const void* p) {
    uint32_t a;
    asm("{ .reg .u64 t; cvta.to.shared.u64 t, %1; cvt.u32.u64 %0, t; }" : "=r"(a) : "l"(p));
    return a;
}
__device__ __forceinline__ void cpasync16(uint32_t dst, const void* src) {
    asm volatile("cp.async.cg.shared.global [%0], [%1], 16;" :: "r"(dst), "l"(src));
}
__device__ __forceinline__ void mma_f16(float* c, const uint32_t* a, const uint32_t* b) {
    asm volatile(
        "mma.sync.aligned.m16n8k16.row.col.f32.f16.f16.f32 "
        "{%0,%1,%2,%3}, {%4,%5,%6,%7}, {%8,%9}, {%0,%1,%2,%3};"
        : "+f"(c[0]), "+f"(c[1]), "+f"(c[2]), "+f"(c[3])
        : "r"(a[0]), "r"(a[1]), "r"(a[2]), "r"(a[3]), "r"(b[0]), "r"(b[1]));
}
__device__ __forceinline__ void ldmx4(uint32_t* r, uint32_t addr) {
    asm volatile("ldmatrix.sync.aligned.m8n8.x4.shared.b16 {%0,%1,%2,%3}, [%4];"
        : "=r"(r[0]), "=r"(r[1]), "=r"(r[2]), "=r"(r[3]) : "r"(addr));
}

// ---------------------------------------------------------------------------
// float -> half packs
// ---------------------------------------------------------------------------
__global__ __launch_bounds__(256) void cvt_f2h_kernel(const float* __restrict__ src,
                                                      __half* __restrict__ dst, int n) {
    int i = (blockIdx.x * 256 + threadIdx.x) * 8;
    if (i < n) {
        float4 v0 = *(const float4*)(src + i);
        float4 v1 = *(const float4*)(src + i + 4);
        __half2* d = (__half2*)(dst + i);
        d[0] = __floats2half2_rn(v0.x, v0.y);
        d[1] = __floats2half2_rn(v0.z, v0.w);
        d[2] = __floats2half2_rn(v1.x, v1.y);
        d[3] = __floats2half2_rn(v1.z, v1.w);
    }
}

__global__ __launch_bounds__(256) void cvt_qkv_kernel(const float* __restrict__ wq,
                                                      const float* __restrict__ wk,
                                                      const float* __restrict__ wv,
                                                      __half* __restrict__ dst) {
    int i = (blockIdx.x * 256 + threadIdx.x) * 8;
    const float* src;
    int off;
    if (i < QDIM * HID)               { src = wq; off = i; }
    else if (i < (QDIM + KDIM) * HID) { src = wk; off = i - QDIM * HID; }
    else                              { src = wv; off = i - (QDIM + KDIM) * HID; }
    float4 v0 = *(const float4*)(src + off);
    float4 v1 = *(const float4*)(src + off + 4);
    __half2* d = (__half2*)(dst + i);
    d[0] = __floats2half2_rn(v0.x, v0.y);
    d[1] = __floats2half2_rn(v0.z, v0.w);
    d[2] = __floats2half2_rn(v1.x, v1.y);
    d[3] = __floats2half2_rn(v1.z, v1.w);
}

// ---------------------------------------------------------------------------
// Shared GEMM mainloop: BM=128, BN=128, BK=64, 256 threads (8 warps 4x2),
// warp tile 32x64. Double-buffered cp.async, ldmatrix fragment loads with
// k-step fragment double-buffering (prefetch kk+1 during kk MMAs).
// ---------------------------------------------------------------------------
#define GPADH 72
#define TILE_H (128 * GPADH)                // 9216 halves per operand tile
#define GSM_TOTAL (4 * TILE_H * 2)          // 73728 B: [A0][A1][B0][B1]

__device__ __forceinline__ void gemm_mainloop(const __half* __restrict__ A,
                                              const __half* __restrict__ B,
                                              __half* As, __half* Bs,
                                              int r0, int c0, int K,
                                              int tid, int wm, int wn,
                                              float acc[2][8][4]) {
#pragma unroll
    for (int mi = 0; mi < 2; mi++)
#pragma unroll
        for (int ni = 0; ni < 8; ni++)
#pragma unroll
            for (int j = 0; j < 4; j++) acc[mi][ni][j] = 0.f;

    const int lane = tid & 31;
    const int l7  = lane & 7;
    const int l8  = (lane >> 3) & 1;
    const int l16 = lane >> 4;

    const uint32_t aoff = (uint32_t)(((wm + l7 + l8 * 8) * GPADH + l16 * 8) * 2);
    const uint32_t boff = (uint32_t)(((wn + l7 + l16 * 8) * GPADH + l8 * 8) * 2);
    const uint32_t asu = s2u(As);
    const uint32_t bsu = s2u(Bs);

    const int T = K >> 6;

    auto load_tile = [&](int t, int s) {
        __half* Ad = As + s * TILE_H;
        __half* Bd = Bs + s * TILE_H;
        const __half* Ap = A + (size_t)r0 * K + t * 64;
        const __half* Bp = B + (size_t)c0 * K + t * 64;
#pragma unroll
        for (int i = 0; i < 4; i++) {
            int ch = tid + i * 256;
            int row = ch >> 3, kc = ch & 7;
            cpasync16(s2u(Ad + row * GPADH + kc * 8), Ap + (size_t)row * K + kc * 8);
            cpasync16(s2u(Bd + row * GPADH + kc * 8), Bp + (size_t)row * K + kc * 8);
        }
        asm volatile("cp.async.commit_group;" ::: "memory");
    };

    uint32_t a[2][2][4], b[2][8][2];
    auto ldfrag = [&](int kk, int pb, uint32_t af, uint32_t bf) {
        ldmx4(a[pb][0], af + kk * 32);
        ldmx4(a[pb][1], af + 16 * GPADH * 2 + kk * 32);
#pragma unroll
        for (int j = 0; j < 4; j++) {
            uint32_t tmp[4];
            ldmx4(tmp, bf + j * 16 * GPADH * 2 + kk * 32);
            b[pb][2 * j][0]     = tmp[0];
            b[pb][2 * j][1]     = tmp[1];
            b[pb][2 * j + 1][0] = tmp[2];
            b[pb][2 * j + 1][1] = tmp[3];
        }
    };

    load_tile(0, 0);

    for (int t = 0; t < T; t++) {
        int s = t & 1;
        if (t + 1 < T) load_tile(t + 1, s ^ 1);
        if (t + 1 < T) asm volatile("cp.async.wait_group 1;" ::: "memory");
        else           asm volatile("cp.async.wait_group 0;" ::: "memory");
        __syncthreads();

        const uint32_t af = asu + (uint32_t)(s * TILE_H * 2) + aoff;
        const uint32_t bf = bsu + (uint32_t)(s * TILE_H * 2) + boff;
        ldfrag(0, 0, af, bf);
#pragma unroll
        for (int kk = 0; kk < 4; kk++) {
            int pb = kk & 1;
            if (kk < 3) ldfrag(kk + 1, pb ^ 1, af, bf);
#pragma unroll
            for (int mi = 0; mi < 2; mi++)
#pragma unroll
                for (int ni = 0; ni < 8; ni++)
                    mma_f16(acc[mi][ni], a[pb][mi], b[pb][ni]);
        }
        __syncthreads();
    }
}

// ---------------------------------------------------------------------------
// Fused QKV GEMM + RMSNorm + RoPE + transpose.
// blockIdx.x in [0,16): Q head; [16,24): K head; [24,32): V head.
// ---------------------------------------------------------------------------
__global__ __launch_bounds__(256, 2) void gemm_qkv_fused(const __half* __restrict__ A,
                                                         const __half* __restrict__ B,
                                                         const float* __restrict__ cosb,
                                                         const float* __restrict__ sinb,
                                                         const float* __restrict__ qw,
                                                         const float* __restrict__ kw) {
    extern __shared__ __half hsm[];
    __half* As = hsm;
    __half* Bs = hsm + 2 * TILE_H;

    const int tid  = threadIdx.x;
    const int warp = tid >> 5;
    const int lane = tid & 31;
    const int wm = (warp >> 1) * 32;
    const int wn = (warp & 1) * 64;
    const int fr = lane >> 2;
    const int fc = lane & 3;

    const int head = blockIdx.x;
    const int r0 = blockIdx.y * 128;

    float acc[2][8][4];
    gemm_mainloop(A, B, As, Bs, r0, head * 128, HID, tid, wm, wn, acc);

    float* S = (float*)hsm;
#pragma unroll
    for (int mi = 0; mi < 2; mi++) {
        int row = wm + mi * 16 + fr;
#pragma unroll
        for (int ni = 0; ni < 8; ni++) {
            int col = wn + ni * 8 + 2 * fc;
            *(float2*)&S[row * 132 + col]       = make_float2(acc[mi][ni][0], acc[mi][ni][1]);
            *(float2*)&S[(row + 8) * 132 + col] = make_float2(acc[mi][ni][2], acc[mi][ni][3]);
        }
    }
    __syncthreads();

    if (head < 24) {
        const float* w = (head < 16) ? qw : kw;
        __half* base = (head < 16)
            ? g_qTh + (size_t)head * Ss * HD
            : g_kTh + (size_t)(head - 16) * Ss * HD;
        int nheads = (head < 16) ? NH : NKV;
#pragma unroll 1
        for (int it = 0; it < 16; it++) {
            int row = it * 8 + warp;
            int glob = r0 + row;
            int b = glob >> 11, s = glob & 2047;
            float x0 = S[row * 132 + lane];
            float x1 = S[row * 132 + lane + 32];
            float x2 = S[row * 132 + lane + 64];
            float x3 = S[row * 132 + lane + 96];
            float ssq = x0 * x0 + x1 * x1 + x2 * x2 + x3 * x3;
#pragma unroll
            for (int o = 16; o; o >>= 1) ssq += __shfl_xor_sync(0xffffffffu, ssq, o);
            float inv = rsqrtf(ssq * (1.0f / 128.0f) + 1e-6f);
            x0 = x0 * inv * w[lane];
            x1 = x1 * inv * w[lane + 32];
            x2 = x2 * inv * w[lane + 64];
            x3 = x3 * inv * w[lane + 96];
            const float* cp = cosb + (size_t)glob * HD;
            const float* sp = sinb + (size_t)glob * HD;
            float c0 = cp[lane], c1 = cp[lane + 32], c2 = cp[lane + 64], c3 = cp[lane + 96];
            float s0 = sp[lane], s1 = sp[lane + 32], s2 = sp[lane + 64], s3 = sp[lane + 96];
            __half* dst = base + ((size_t)b * nheads * Ss + s) * HD;
            dst[lane]      = __float2half_rn(x0 * c0 - x2 * s0);
            dst[lane + 32] = __float2half_rn(x1 * c1 - x3 * s1);
            dst[lane + 64] = __float2half_rn(x2 * c2 + x0 * s2);
            dst[lane + 96] = __float2half_rn(x3 * c3 + x1 * s3);
        }
    } else {
        int h = head - 24;
        int b = r0 >> 11, s0 = r0 & 2047;
        __half* dst = g_vTh + ((size_t)b * NKV + h) * Ss * HD;
#pragma unroll 1
        for (int it = 0; it < 16; it++) {
            int d = it * 8 + warp;
#pragma unroll
            for (int j = 0; j < 4; j++) {
                float v = S[(lane + 32 * j) * 132 + d];
                dst[(size_t)d * Ss + s0 + lane + 32 * j] = __float2half_rn(v);
            }
        }
    }
}

// ---------------------------------------------------------------------------
// O-projection GEMM
// ---------------------------------------------------------------------------
__global__ __launch_bounds__(256, 2) void gemm_f16(const __half* __restrict__ A,
                                                   const __half* __restrict__ B,
                                                   float* __restrict__ C,
                                                   int M, int N, int K) {
    extern __shared__ __half hsm[];
    __half* As = hsm;
    __half* Bs = hsm + 2 * TILE_H;

    const int tid  = threadIdx.x;
    const int warp = tid >> 5;
    const int lid  = tid & 31;
    const int wm = (warp >> 1) * 32;
    const int wn = (warp & 1) * 64;
    const int fr = lid >> 2;
    const int fc = lid & 3;

    const int r0 = blockIdx.y * 128;
    const int c0 = blockIdx.x * 128;

    float acc[2][8][4];
    gemm_mainloop(A, B, As, Bs, r0, c0, K, tid, wm, wn, acc);

#pragma unroll
    for (int mi = 0; mi < 2; mi++) {
        int row = r0 + wm + mi * 16 + fr;
        float* cp0 = C + (size_t)row * N + c0 + wn + fc * 2;
        float* cp1 = C + (size_t)(row + 8) * N + c0 + wn + fc * 2;
#pragma unroll
        for (int ni = 0; ni < 8; ni++) {
            *(float2*)(cp0 + ni * 8) = make_float2(acc[mi][ni][0], acc[mi][ni][1]);
            *(float2*)(cp1 + ni * 8) = make_float2(acc[mi][ni][2], acc[mi][ni][3]);
        }
    }
}

// ---------------------------------------------------------------------------
// fp16 tensorized flash attention, causal, GQA — exact R7 known-good layout.
// Half region: Qs[64*136] | Ks[2][64*136] | Vt[2][128*72] | Ps[64*72]
// Float region: Ssc[64*68] | corr[64] | linv[64]
// ---------------------------------------------------------------------------
#define FQP 136
#define FVP 72
#define FSP 68
#define HOFF_KS   (64 * FQP)
#define HOFF_VT   (HOFF_KS + 2 * 64 * FQP)
#define HOFF_PS   (HOFF_VT + 2 * 128 * FVP)
#define FSM_TOTAL (98304 + 64*FSP*4 + 512)

__global__ __launch_bounds__(256, 1) void flash_mma_kernel() {
    extern __shared__ char fsm[];
    __half* Qs  = (__half*)fsm;
    __half* Ksb = Qs + HOFF_KS;
    __half* Vtb = Qs + HOFF_VT;
    __half* Ps  = Qs + HOFF_PS;
    float* Ssc  = (float*)(fsm + 98304);
    float* corr = Ssc + 64 * FSP;
    float* linv = corr + 64;

    const int tid  = threadIdx.x;
    const int warp = tid >> 5;
    const int lane = tid & 31;
    const int fr = lane >> 2;
    const int fc = lane & 3;
    const int l7  = lane & 7;
    const int l8  = (lane >> 3) & 1;
    const int l16 = lane >> 4;
    const int wmS = (warp >> 1) * 16;
    const int wnS = (warp & 1) * 32;
    const int wmO = wmS;
    const int wnO = (warp & 1) * 64;

    const int q0 = blockIdx.x * 64;
    const int h  = blockIdx.y;
    const int b  = blockIdx.z;
    const int hk = h >> 1;

    const __half* qb  = g_qTh + (((size_t)b * NH + h) * Ss + q0) * HD;
    const __half* kb  = g_kTh + ((size_t)b * NKV + hk) * Ss * HD;
    const __half* vtb = g_vTh + ((size_t)b * NKV + hk) * Ss * HD;

    const uint32_t qsu = s2u(Qs);
    const uint32_t ksu = s2u(Ksb);
    const uint32_t vsu = s2u(Vtb);
    const uint32_t psu = s2u(Ps);
    const uint32_t qoff = (uint32_t)(((wmS + l7 + l8 * 8) * FQP + l16 * 8) * 2);
    const uint32_t koff = (uint32_t)(((wnS + l7 + l16 * 8) * FQP + l8 * 8) * 2);
    const uint32_t poff = (uint32_t)(((wmO + l7 + l8 * 8) * FVP + l16 * 8) * 2);
    const uint32_t voff = (uint32_t)(((wnO + l7 + l16 * 8) * FVP + l8 * 8) * 2);

    const int srow = tid >> 2;
    const int ssub = tid & 3;
    float m_old = -1e30f, l_old = 0.f;

    float oa[8][4];
#pragma unroll
    for (int nf = 0; nf < 8; nf++)
#pragma unroll
        for (int j = 0; j < 4; j++) oa[nf][j] = 0.f;

    auto loadQ = [&]() {
#pragma unroll
        for (int i = 0; i < 4; i++) {
            int ch = tid + i * 256;
            int row = ch >> 4, kc = ch & 15;
            cpasync16(s2u(Qs + row * FQP + kc * 8), qb + (size_t)row * HD + kc * 8);
        }
    };
    auto loadK = [&](int j, int s) {
        __half* Kd = Ksb + s * 64 * FQP;
        const __half* src = kb + (size_t)(j * 64) * HD;
#pragma unroll
        for (int i = 0; i < 4; i++) {
            int ch = tid + i * 256;
            int row = ch >> 4, kc = ch & 15;
            cpasync16(s2u(Kd + row * FQP + kc * 8), src + (size_t)row * HD + kc * 8);
        }
    };
    auto loadV = [&](int j, int s) {
        __half* Vd = Vtb + s * 128 * FVP;
#pragma unroll
        for (int i = 0; i < 4; i++) {
            int ch = tid + i * 256;
            int row = ch >> 3, kc = ch & 7;
            cpasync16(s2u(Vd + row * FVP + kc * 8), vtb + (size_t)row * Ss + j * 64 + kc * 8);
        }
    };

    const int nt = blockIdx.x + 1;
    loadQ(); loadK(0, 0); loadV(0, 0);
    asm volatile("cp.async.commit_group;" ::: "memory");

    for (int j = 0; j < nt; j++) {
        int s = j & 1;
        if (j + 1 < nt) {
            loadK(j + 1, s ^ 1); loadV(j + 1, s ^ 1);
            asm volatile("cp.async.commit_group;" ::: "memory");
            asm volatile("cp.async.wait_group 1;" ::: "memory");
        } else {
            asm volatile("cp.async.wait_group 0;" ::: "memory");
        }
        __syncthreads();

        // ---- S = Q K^T ----
        const uint32_t kf = ksu + (uint32_t)(s * 64 * FQP * 2) + koff;
        float sa[4][4];
#pragma unroll
        for (int nf = 0; nf < 4; nf++)
#pragma unroll
            for (int t = 0; t < 4; t++) sa[nf][t] = 0.f;
#pragma unroll
        for (int kk = 0; kk < 8; kk++) {
            uint32_t a[4], bfr[4][2];
            ldmx4(a, qsu + qoff + kk * 32);
#pragma unroll
            for (int jj = 0; jj < 2; jj++) {
                uint32_t tmp[4];
                ldmx4(tmp, kf + jj * 16 * FQP * 2 + kk * 32);
                bfr[2 * jj][0]     = tmp[0];
                bfr[2 * jj][1]     = tmp[1];
                bfr[2 * jj + 1][0] = tmp[2];
                bfr[2 * jj + 1][1] = tmp[3];
            }
#pragma unroll
            for (int nf = 0; nf < 4; nf++) mma_f16(sa[nf], a, bfr[nf]);
        }
#pragma unroll
        for (int nf = 0; nf < 4; nf++) {
            int col = wnS + nf * 8 + 2 * fc;
            *(float2*)&Ssc[(wmS + fr) * FSP + col]     = make_float2(sa[nf][0], sa[nf][1]);
            *(float2*)&Ssc[(wmS + fr + 8) * FSP + col] = make_float2(sa[nf][2], sa[nf][3]);
        }
        __syncthreads();

        // ---- online softmax ----
        {
            float sv[16];
            float mx = -1e30f;
            int qglob = q0 + srow;
#pragma unroll
            for (int i = 0; i < 16; i++) {
                int c = ssub + 4 * i;
                float val = Ssc[srow * FSP + c] * SCALE;
                if (j * 64 + c > qglob) val = -1e9f;
                sv[i] = val;
                mx = fmaxf(mx, val);
            }
            mx = fmaxf(mx, __shfl_xor_sync(0xffffffffu, mx, 1));
            mx = fmaxf(mx, __shfl_xor_sync(0xffffffffu, mx, 2));
            float mnew = fmaxf(m_old, mx);
            float cr = __expf(m_old - mnew);
            float psum = 0.f;
#pragma unroll
            for (int i = 0; i < 16; i++) {
                float p = __expf(sv[i] - mnew);
                psum += p;
                Ps[srow * FVP + ssub + 4 * i] = __float2half_rn(p);
            }
            psum += __shfl_xor_sync(0xffffffffu, psum, 1);
            psum += __shfl_xor_sync(0xffffffffu, psum, 2);
            l_old = l_old * cr + psum;
            m_old = mnew;
            if (ssub == 0) corr[srow] = cr;
        }
        __syncthreads();

        // ---- O = O*corr + P V ----
        const uint32_t vf = vsu + (uint32_t)(s * 128 * FVP * 2) + voff;
        {
            float cr0 = corr[wmO + fr];
            float cr1 = corr[wmO + fr + 8];
#pragma unroll
            for (int nf = 0; nf < 8; nf++) {
                oa[nf][0] *= cr0; oa[nf][1] *= cr0;
                oa[nf][2] *= cr1; oa[nf][3] *= cr1;
            }
        }
#pragma unroll
        for (int kk = 0; kk < 4; kk++) {
            uint32_t a[4], bfr[8][2];
            ldmx4(a, psu + poff + kk * 32);
#pragma unroll
            for (int jj = 0; jj < 4; jj++) {
                uint32_t tmp[4];
                ldmx4(tmp, vf + jj * 16 * FVP * 2 + kk * 32);
                bfr[2 * jj][0]     = tmp[0];
                bfr[2 * jj][1]     = tmp[1];
                bfr[2 * jj + 1][0] = tmp[2];
                bfr[2 * jj + 1][1] = tmp[3];
            }
#pragma unroll
            for (int nf = 0; nf < 8; nf++) mma_f16(oa[nf], a, bfr[nf]);
        }
    }

    if (ssub == 0) linv[srow] = 1.0f / l_old;
    __syncthreads();

    float i0 = linv[wmO + fr];
    float i1 = linv[wmO + fr + 8];
    int row0 = q0 + wmO + fr;
    __half* d0 = g_attnH + ((size_t)(b * Ss + row0) * NH + h) * HD + wnO + 2 * fc;
    __half* d1 = g_attnH + ((size_t)(b * Ss + row0 + 8) * NH + h) * HD + wnO + 2 * fc;
#pragma unroll
    for (int nf = 0; nf < 8; nf++) {
        *(__half2*)(d0 + nf * 8) = __floats2half2_rn(oa[nf][0] * i0, oa[nf][1] * i0);
        *(__half2*)(d1 + nf * 8) = __floats2half2_rn(oa[nf][2] * i1, oa[nf][3] * i1);
    }
}

// ---------------------------------------------------------------------------
extern "C" void kernel_launch(void* const* d_in, const int* in_sizes, int n_in,
                              void* d_out, int out_size) {
    const float* x    = (const float*)d_in[0];
    const float* cosb = (const float*)d_in[1];
    const float* sinb = (const float*)d_in[2];
    const float* Wq = (const float*)d_in[4];
    const float* Wk = (const float*)d_in[5];
    const float* Wv = (const float*)d_in[6];
    const float* Wo = (const float*)d_in[7];
    const float* qw = (const float*)d_in[8];
    const float* kw = (const float*)d_in[9];
    float* out = (float*)d_out;

    __half *xH, *wqkvH, *woH, *attnH;
    cudaGetSymbolAddress((void**)&xH,    g_xH);
    cudaGetSymbolAddress((void**)&wqkvH, g_wqkvH);
    cudaGetSymbolAddress((void**)&woH,   g_woH);
    cudaGetSymbolAddress((void**)&attnH, g_attnH);

    cudaFuncSetAttribute(gemm_qkv_fused, cudaFuncAttributeMaxDynamicSharedMemorySize, GSM_TOTAL);
    cudaFuncSetAttribute(gemm_f16, cudaFuncAttributeMaxDynamicSharedMemorySize, GSM_TOTAL);
    cudaFuncSetAttribute(flash_mma_kernel, cudaFuncAttributeMaxDynamicSharedMemorySize, FSM_TOTAL);

    // fp16 packs
    cvt_f2h_kernel<<<(MROWS * HID) / 2048, 256>>>(x, xH, MROWS * HID);
    cvt_qkv_kernel<<<(NQKV * HID) / 2048, 256>>>(Wq, Wk, Wv, wqkvH);
    cvt_f2h_kernel<<<(HID * QDIM) / 2048, 256>>>(Wo, woH, HID * QDIM);

    // Fused QKV projection + RMSNorm + RoPE + transpose
    gemm_qkv_fused<<<dim3(NQKV / 128, MROWS / 128), 256, GSM_TOTAL>>>(
        xH, wqkvH, cosb, sinb, qw, kw);

    // fp16 tensorized causal flash attention
    flash_mma_kernel<<<dim3(Ss / 64, NH, Bb), 256, FSM_TOTAL>>>();

    // Output projection
    gemm_f16<<<dim3(HID / 128, MROWS / 128), 256, GSM_TOTAL>>>(attnH, woH, out, MROWS, HID, QDIM);
}

// round 15
// speedup vs baseline: 1.0728x; 1.0728x over previous
#include <cuda_runtime.h>
#include <cuda_fp16.h>
#include <cstdint>

// Problem constants
#define Bb   2
#define Ss   2048
#define HID  1024
#define NH   16
#define NKV  8
#define HD   128
#define MROWS (Bb*Ss)          // 4096
#define QDIM (NH*HD)           // 2048
#define KDIM (NKV*HD)          // 1024
#define NQKV (QDIM + 2*KDIM)   // 4096 combined
#define SCALE 0.08838834764831845f

// ---------------------------------------------------------------------------
// Scratch (static device memory; no allocation APIs)
// ---------------------------------------------------------------------------
__device__ __half g_qTh[(size_t)Bb * NH * Ss * HD];    // [b][h][s][d]
__device__ __half g_kTh[(size_t)Bb * NKV * Ss * HD];   // [b][hk][s][d]
__device__ __half g_vTh[(size_t)Bb * NKV * Ss * HD];   // [b][hk][d][s] transposed
__device__ __half g_attnH[(size_t)MROWS * QDIM];       // flash output (half)
__device__ __half g_xH[(size_t)MROWS * HID];
__device__ __half g_wqkvH[(size_t)NQKV * HID];         // [Wq;Wk;Wv] rows
__device__ __half g_woH[(size_t)HID * QDIM];

__device__ __forceinline__ uint32_t s2u(const void* p) {
    uint32_t a;
    asm("{ .reg .u64 t; cvta.to.shared.u64 t, %1; cvt.u32.u64 %0, t; }" : "=r"(a) : "l"(p));
    return a;
}
__device__ __forceinline__ void cpasync16(uint32_t dst, const void* src) {
    asm volatile("cp.async.cg.shared.global [%0], [%1], 16;" :: "r"(dst), "l"(src));
}
__device__ __forceinline__ void mma_f16(float* c, const uint32_t* a, const uint32_t* b) {
    asm volatile(
        "mma.sync.aligned.m16n8k16.row.col.f32.f16.f16.f32 "
        "{%0,%1,%2,%3}, {%4,%5,%6,%7}, {%8,%9}, {%0,%1,%2,%3};"
        : "+f"(c[0]), "+f"(c[1]), "+f"(c[2]), "+f"(c[3])
        : "r"(a[0]), "r"(a[1]), "r"(a[2]), "r"(a[3]), "r"(b[0]), "r"(b[1]));
}
__device__ __forceinline__ void ldmx4(uint32_t* r, uint32_t addr) {
    asm volatile("ldmatrix.sync.aligned.m8n8.x4.shared.b16 {%0,%1,%2,%3}, [%4];"
        : "=r"(r[0]), "=r"(r[1]), "=r"(r[2]), "=r"(r[3]) : "r"(addr));
}

// ---------------------------------------------------------------------------
// float -> half packs
// ---------------------------------------------------------------------------
__global__ __launch_bounds__(256) void cvt_f2h_kernel(const float* __restrict__ src,
                                                      __half* __restrict__ dst, int n) {
    int i = (blockIdx.x * 256 + threadIdx.x) * 8;
    if (i < n) {
        float4 v0 = *(const float4*)(src + i);
        float4 v1 = *(const float4*)(src + i + 4);
        __half2* d = (__half2*)(dst + i);
        d[0] = __floats2half2_rn(v0.x, v0.y);
        d[1] = __floats2half2_rn(v0.z, v0.w);
        d[2] = __floats2half2_rn(v1.x, v1.y);
        d[3] = __floats2half2_rn(v1.z, v1.w);
    }
}

__global__ __launch_bounds__(256) void cvt_qkv_kernel(const float* __restrict__ wq,
                                                      const float* __restrict__ wk,
                                                      const float* __restrict__ wv,
                                                      __half* __restrict__ dst) {
    int i = (blockIdx.x * 256 + threadIdx.x) * 8;
    const float* src;
    int off;
    if (i < QDIM * HID)               { src = wq; off = i; }
    else if (i < (QDIM + KDIM) * HID) { src = wk; off = i - QDIM * HID; }
    else                              { src = wv; off = i - (QDIM + KDIM) * HID; }
    float4 v0 = *(const float4*)(src + off);
    float4 v1 = *(const float4*)(src + off + 4);
    __half2* d = (__half2*)(dst + i);
    d[0] = __floats2half2_rn(v0.x, v0.y);
    d[1] = __floats2half2_rn(v0.z, v0.w);
    d[2] = __floats2half2_rn(v1.x, v1.y);
    d[3] = __floats2half2_rn(v1.z, v1.w);
}

// ---------------------------------------------------------------------------
// Shared GEMM mainloop (R7 known-good): BM=128, BN=128, BK=64, 256 threads
// (8 warps 4x2), warp tile 32x64. Double-buffered cp.async, ldmatrix frags.
// ---------------------------------------------------------------------------
#define GPADH 72
#define TILE_H (128 * GPADH)                // 9216 halves per operand tile
#define GSM_TOTAL (4 * TILE_H * 2)          // 73728 B: [A0][A1][B0][B1]

__device__ __forceinline__ void gemm_mainloop(const __half* __restrict__ A,
                                              const __half* __restrict__ B,
                                              __half* As, __half* Bs,
                                              int r0, int c0, int K,
                                              int tid, int wm, int wn,
                                              float acc[2][8][4]) {
#pragma unroll
    for (int mi = 0; mi < 2; mi++)
#pragma unroll
        for (int ni = 0; ni < 8; ni++)
#pragma unroll
            for (int j = 0; j < 4; j++) acc[mi][ni][j] = 0.f;

    const int lane = tid & 31;
    const int l7  = lane & 7;
    const int l8  = (lane >> 3) & 1;
    const int l16 = lane >> 4;

    const uint32_t aoff = (uint32_t)(((wm + l7 + l8 * 8) * GPADH + l16 * 8) * 2);
    const uint32_t boff = (uint32_t)(((wn + l7 + l16 * 8) * GPADH + l8 * 8) * 2);
    const uint32_t asu = s2u(As);
    const uint32_t bsu = s2u(Bs);

    const int T = K >> 6;

    auto load_tile = [&](int t, int s) {
        __half* Ad = As + s * TILE_H;
        __half* Bd = Bs + s * TILE_H;
        const __half* Ap = A + (size_t)r0 * K + t * 64;
        const __half* Bp = B + (size_t)c0 * K + t * 64;
#pragma unroll
        for (int i = 0; i < 4; i++) {
            int ch = tid + i * 256;
            int row = ch >> 3, kc = ch & 7;
            cpasync16(s2u(Ad + row * GPADH + kc * 8), Ap + (size_t)row * K + kc * 8);
            cpasync16(s2u(Bd + row * GPADH + kc * 8), Bp + (size_t)row * K + kc * 8);
        }
        asm volatile("cp.async.commit_group;" ::: "memory");
    };

    load_tile(0, 0);

    for (int t = 0; t < T; t++) {
        int s = t & 1;
        if (t + 1 < T) load_tile(t + 1, s ^ 1);
        if (t + 1 < T) asm volatile("cp.async.wait_group 1;" ::: "memory");
        else           asm volatile("cp.async.wait_group 0;" ::: "memory");
        __syncthreads();

        const uint32_t af = asu + (uint32_t)(s * TILE_H * 2) + aoff;
        const uint32_t bf = bsu + (uint32_t)(s * TILE_H * 2) + boff;
#pragma unroll
        for (int kk = 0; kk < 4; kk++) {
            uint32_t a[2][4], b[8][2];
            ldmx4(a[0], af + kk * 32);
            ldmx4(a[1], af + 16 * GPADH * 2 + kk * 32);
#pragma unroll
            for (int j = 0; j < 4; j++) {
                uint32_t tmp[4];
                ldmx4(tmp, bf + j * 16 * GPADH * 2 + kk * 32);
                b[2 * j][0]     = tmp[0];
                b[2 * j][1]     = tmp[1];
                b[2 * j + 1][0] = tmp[2];
                b[2 * j + 1][1] = tmp[3];
            }
#pragma unroll
            for (int mi = 0; mi < 2; mi++)
#pragma unroll
                for (int ni = 0; ni < 8; ni++)
                    mma_f16(acc[mi][ni], a[mi], b[ni]);
        }
        __syncthreads();
    }
}

// ---------------------------------------------------------------------------
// Fused QKV GEMM + RMSNorm + RoPE + transpose.
// blockIdx.x in [0,16): Q head; [16,24): K head; [24,32): V head.
// ---------------------------------------------------------------------------
__global__ __launch_bounds__(256, 2) void gemm_qkv_fused(const __half* __restrict__ A,
                                                         const __half* __restrict__ B,
                                                         const float* __restrict__ cosb,
                                                         const float* __restrict__ sinb,
                                                         const float* __restrict__ qw,
                                                         const float* __restrict__ kw) {
    extern __shared__ __half hsm[];
    __half* As = hsm;
    __half* Bs = hsm + 2 * TILE_H;

    const int tid  = threadIdx.x;
    const int warp = tid >> 5;
    const int lane = tid & 31;
    const int wm = (warp >> 1) * 32;
    const int wn = (warp & 1) * 64;
    const int fr = lane >> 2;
    const int fc = lane & 3;

    const int head = blockIdx.x;
    const int r0 = blockIdx.y * 128;

    float acc[2][8][4];
    gemm_mainloop(A, B, As, Bs, r0, head * 128, HID, tid, wm, wn, acc);

    float* S = (float*)hsm;
#pragma unroll
    for (int mi = 0; mi < 2; mi++) {
        int row = wm + mi * 16 + fr;
#pragma unroll
        for (int ni = 0; ni < 8; ni++) {
            int col = wn + ni * 8 + 2 * fc;
            *(float2*)&S[row * 132 + col]       = make_float2(acc[mi][ni][0], acc[mi][ni][1]);
            *(float2*)&S[(row + 8) * 132 + col] = make_float2(acc[mi][ni][2], acc[mi][ni][3]);
        }
    }
    __syncthreads();

    if (head < 24) {
        const float* w = (head < 16) ? qw : kw;
        __half* base = (head < 16)
            ? g_qTh + (size_t)head * Ss * HD
            : g_kTh + (size_t)(head - 16) * Ss * HD;
        int nheads = (head < 16) ? NH : NKV;
#pragma unroll 1
        for (int it = 0; it < 16; it++) {
            int row = it * 8 + warp;
            int glob = r0 + row;
            int b = glob >> 11, s = glob & 2047;
            float x0 = S[row * 132 + lane];
            float x1 = S[row * 132 + lane + 32];
            float x2 = S[row * 132 + lane + 64];
            float x3 = S[row * 132 + lane + 96];
            float ssq = x0 * x0 + x1 * x1 + x2 * x2 + x3 * x3;
#pragma unroll
            for (int o = 16; o; o >>= 1) ssq += __shfl_xor_sync(0xffffffffu, ssq, o);
            float inv = rsqrtf(ssq * (1.0f / 128.0f) + 1e-6f);
            x0 = x0 * inv * w[lane];
            x1 = x1 * inv * w[lane + 32];
            x2 = x2 * inv * w[lane + 64];
            x3 = x3 * inv * w[lane + 96];
            const float* cp = cosb + (size_t)glob * HD;
            const float* sp = sinb + (size_t)glob * HD;
            float c0 = cp[lane], c1 = cp[lane + 32], c2 = cp[lane + 64], c3 = cp[lane + 96];
            float s0 = sp[lane], s1 = sp[lane + 32], s2 = sp[lane + 64], s3 = sp[lane + 96];
            __half* dst = base + ((size_t)b * nheads * Ss + s) * HD;
            dst[lane]      = __float2half_rn(x0 * c0 - x2 * s0);
            dst[lane + 32] = __float2half_rn(x1 * c1 - x3 * s1);
            dst[lane + 64] = __float2half_rn(x2 * c2 + x0 * s2);
            dst[lane + 96] = __float2half_rn(x3 * c3 + x1 * s3);
        }
    } else {
        int h = head - 24;
        int b = r0 >> 11, s0 = r0 & 2047;
        __half* dst = g_vTh + ((size_t)b * NKV + h) * Ss * HD;
#pragma unroll 1
        for (int it = 0; it < 16; it++) {
            int d = it * 8 + warp;
#pragma unroll
            for (int j = 0; j < 4; j++) {
                float v = S[(lane + 32 * j) * 132 + d];
                dst[(size_t)d * Ss + s0 + lane + 32 * j] = __float2half_rn(v);
            }
        }
    }
}

// ---------------------------------------------------------------------------
// O-projection GEMM
// ---------------------------------------------------------------------------
__global__ __launch_bounds__(256, 2) void gemm_f16(const __half* __restrict__ A,
                                                   const __half* __restrict__ B,
                                                   float* __restrict__ C,
                                                   int M, int N, int K) {
    extern __shared__ __half hsm[];
    __half* As = hsm;
    __half* Bs = hsm + 2 * TILE_H;

    const int tid  = threadIdx.x;
    const int warp = tid >> 5;
    const int lid  = tid & 31;
    const int wm = (warp >> 1) * 32;
    const int wn = (warp & 1) * 64;
    const int fr = lid >> 2;
    const int fc = lid & 3;

    const int r0 = blockIdx.y * 128;
    const int c0 = blockIdx.x * 128;

    float acc[2][8][4];
    gemm_mainloop(A, B, As, Bs, r0, c0, K, tid, wm, wn, acc);

#pragma unroll
    for (int mi = 0; mi < 2; mi++) {
        int row = r0 + wm + mi * 16 + fr;
        float* cp0 = C + (size_t)row * N + c0 + wn + fc * 2;
        float* cp1 = C + (size_t)(row + 8) * N + c0 + wn + fc * 2;
#pragma unroll
        for (int ni = 0; ni < 8; ni++) {
            *(float2*)(cp0 + ni * 8) = make_float2(acc[mi][ni][0], acc[mi][ni][1]);
            *(float2*)(cp1 + ni * 8) = make_float2(acc[mi][ni][2], acc[mi][ni][3]);
        }
    }
}

// ---------------------------------------------------------------------------
// fp16 tensorized flash attention, causal, GQA.
// K SINGLE-buffered (K(j+1) issued after post-S barrier), V double-buffered.
// Half region: Qs[64*136] | Ks[64*136] | Vt[2][128*72] | Ps[64*72]  (80896 B)
// Float region @80896: Ssc[64*68] | corr[64] | linv[64]             (17920 B)
// Total 99072 B -> 2 CTAs/SM.
// ---------------------------------------------------------------------------
#define FQP 136
#define FVP 72
#define FSP 68
#define HOFF_KS   (64 * FQP)                 // 8704
#define HOFF_VT   (HOFF_KS + 64 * FQP)       // 17408
#define HOFF_PS   (HOFF_VT + 2 * 128 * FVP)  // 35840
#define FSM_TOTAL (80896 + 64*FSP*4 + 512 + 128)   // 99072

__global__ __launch_bounds__(256, 2) void flash_mma_kernel() {
    extern __shared__ char fsm[];
    __half* Qs  = (__half*)fsm;
    __half* Ksb = Qs + HOFF_KS;
    __half* Vtb = Qs + HOFF_VT;
    __half* Ps  = Qs + HOFF_PS;
    float* Ssc  = (float*)(fsm + 80896);
    float* corr = Ssc + 64 * FSP;
    float* linv = corr + 64;

    const int tid  = threadIdx.x;
    const int warp = tid >> 5;
    const int lane = tid & 31;
    const int fr = lane >> 2;
    const int fc = lane & 3;
    const int l7  = lane & 7;
    const int l8  = (lane >> 3) & 1;
    const int l16 = lane >> 4;
    const int wmS = (warp >> 1) * 16;
    const int wnS = (warp & 1) * 32;
    const int wmO = wmS;
    const int wnO = (warp & 1) * 64;

    const int q0 = blockIdx.x * 64;
    const int h  = blockIdx.y;
    const int b  = blockIdx.z;
    const int hk = h >> 1;

    const __half* qb  = g_qTh + (((size_t)b * NH + h) * Ss + q0) * HD;
    const __half* kb  = g_kTh + ((size_t)b * NKV + hk) * Ss * HD;
    const __half* vtb = g_vTh + ((size_t)b * NKV + hk) * Ss * HD;

    const uint32_t qsu = s2u(Qs);
    const uint32_t ksu = s2u(Ksb);
    const uint32_t vsu = s2u(Vtb);
    const uint32_t psu = s2u(Ps);
    const uint32_t qoff = (uint32_t)(((wmS + l7 + l8 * 8) * FQP + l16 * 8) * 2);
    const uint32_t koff = (uint32_t)(((wnS + l7 + l16 * 8) * FQP + l8 * 8) * 2);
    const uint32_t poff = (uint32_t)(((wmO + l7 + l8 * 8) * FVP + l16 * 8) * 2);
    const uint32_t voff = (uint32_t)(((wnO + l7 + l16 * 8) * FVP + l8 * 8) * 2);

    const int srow = tid >> 2;
    const int ssub = tid & 3;
    float m_old = -1e30f, l_old = 0.f;

    float oa[8][4];
#pragma unroll
    for (int nf = 0; nf < 8; nf++)
#pragma unroll
        for (int j = 0; j < 4; j++) oa[nf][j] = 0.f;

    auto loadQ = [&]() {
#pragma unroll
        for (int i = 0; i < 4; i++) {
            int ch = tid + i * 256;
            int row = ch >> 4, kc = ch & 15;
            cpasync16(s2u(Qs + row * FQP + kc * 8), qb + (size_t)row * HD + kc * 8);
        }
    };
    auto loadK = [&](int j) {              // single buffer
        const __half* src = kb + (size_t)(j * 64) * HD;
#pragma unroll
        for (int i = 0; i < 4; i++) {
            int ch = tid + i * 256;
            int row = ch >> 4, kc = ch & 15;
            cpasync16(s2u(Ksb + row * FQP + kc * 8), src + (size_t)row * HD + kc * 8);
        }
    };
    auto loadV = [&](int j, int s) {       // double buffer
        __half* Vd = Vtb + s * 128 * FVP;
#pragma unroll
        for (int i = 0; i < 4; i++) {
            int ch = tid + i * 256;
            int row = ch >> 3, kc = ch & 7;
            cpasync16(s2u(Vd + row * FVP + kc * 8), vtb + (size_t)row * Ss + j * 64 + kc * 8);
        }
    };

    const int nt = blockIdx.x + 1;
    loadQ(); loadK(0); loadV(0, 0);
    asm volatile("cp.async.commit_group;" ::: "memory");

    for (int j = 0; j < nt; j++) {
        // Group j (K(j), V(j)) was committed one iteration ago (or prologue).
        asm volatile("cp.async.wait_group 0;" ::: "memory");
        __syncthreads();                     // (A) K(j)/V(j) visible to all

        // ---- S = Q K^T ----
        float sa[4][4];
#pragma unroll
        for (int nf = 0; nf < 4; nf++)
#pragma unroll
            for (int t = 0; t < 4; t++) sa[nf][t] = 0.f;
#pragma unroll
        for (int kk = 0; kk < 8; kk++) {
            uint32_t a[4], bfr[4][2];
            ldmx4(a, qsu + qoff + kk * 32);
#pragma unroll
            for (int jj = 0; jj < 2; jj++) {
                uint32_t tmp[4];
                ldmx4(tmp, ksu + koff + jj * 16 * FQP * 2 + kk * 32);
                bfr[2 * jj][0]     = tmp[0];
                bfr[2 * jj][1]     = tmp[1];
                bfr[2 * jj + 1][0] = tmp[2];
                bfr[2 * jj + 1][1] = tmp[3];
            }
#pragma unroll
            for (int nf = 0; nf < 4; nf++) mma_f16(sa[nf], a, bfr[nf]);
        }
#pragma unroll
        for (int nf = 0; nf < 4; nf++) {
            int col = wnS + nf * 8 + 2 * fc;
            *(float2*)&Ssc[(wmS + fr) * FSP + col]     = make_float2(sa[nf][0], sa[nf][1]);
            *(float2*)&Ssc[(wmS + fr + 8) * FSP + col] = make_float2(sa[nf][2], sa[nf][3]);
        }
        __syncthreads();                     // (B) all done reading Ks, Ssc ready

        // Prefetch next K/V: safe to overwrite Ks now; V goes to other buffer.
        if (j + 1 < nt) {
            loadK(j + 1);
            loadV(j + 1, (j + 1) & 1);
            asm volatile("cp.async.commit_group;" ::: "memory");
        }

        // ---- online softmax ----
        {
            float sv[16];
            float mx = -1e30f;
#pragma unroll
            for (int i = 0; i < 16; i++) {
                sv[i] = Ssc[srow * FSP + ssub + 4 * i] * SCALE;
            }
            if (j == nt - 1) {               // only the diagonal tile is masked
                int qglob = q0 + srow;
#pragma unroll
                for (int i = 0; i < 16; i++) {
                    int c = ssub + 4 * i;
                    if (j * 64 + c > qglob) sv[i] = -1e9f;
                }
            }
#pragma unroll
            for (int i = 0; i < 16; i++) mx = fmaxf(mx, sv[i]);
            mx = fmaxf(mx, __shfl_xor_sync(0xffffffffu, mx, 1));
            mx = fmaxf(mx, __shfl_xor_sync(0xffffffffu, mx, 2));
            float mnew = fmaxf(m_old, mx);
            float cr = __expf(m_old - mnew);
            float psum = 0.f;
#pragma unroll
            for (int i = 0; i < 16; i++) {
                float p = __expf(sv[i] - mnew);
                psum += p;
                Ps[srow * FVP + ssub + 4 * i] = __float2half_rn(p);
            }
            psum += __shfl_xor_sync(0xffffffffu, psum, 1);
            psum += __shfl_xor_sync(0xffffffffu, psum, 2);
            l_old = l_old * cr + psum;
            m_old = mnew;
            if (ssub == 0) corr[srow] = cr;
        }
        __syncthreads();                     // (C) Ps/corr visible

        // ---- O = O*corr + P V ----
        const uint32_t vf = vsu + (uint32_t)((j & 1) * 128 * FVP * 2) + voff;
        {
            float cr0 = corr[wmO + fr];
            float cr1 = corr[wmO + fr + 8];
#pragma unroll
            for (int nf = 0; nf < 8; nf++) {
                oa[nf][0] *= cr0; oa[nf][1] *= cr0;
                oa[nf][2] *= cr1; oa[nf][3] *= cr1;
            }
        }
#pragma unroll
        for (int kk = 0; kk < 4; kk++) {
            uint32_t a[4], bfr[8][2];
            ldmx4(a, psu + poff + kk * 32);
#pragma unroll
            for (int jj = 0; jj < 4; jj++) {
                uint32_t tmp[4];
                ldmx4(tmp, vf + jj * 16 * FVP * 2 + kk * 32);
                bfr[2 * jj][0]     = tmp[0];
                bfr[2 * jj][1]     = tmp[1];
                bfr[2 * jj + 1][0] = tmp[2];
                bfr[2 * jj + 1][1] = tmp[3];
            }
#pragma unroll
            for (int nf = 0; nf < 8; nf++) mma_f16(oa[nf], a, bfr[nf]);
        }
    }

    if (ssub == 0) linv[srow] = 1.0f / l_old;
    __syncthreads();

    float i0 = linv[wmO + fr];
    float i1 = linv[wmO + fr + 8];
    int row0 = q0 + wmO + fr;
    __half* d0 = g_attnH + ((size_t)(b * Ss + row0) * NH + h) * HD + wnO + 2 * fc;
    __half* d1 = g_attnH + ((size_t)(b * Ss + row0 + 8) * NH + h) * HD + wnO + 2 * fc;
#pragma unroll
    for (int nf = 0; nf < 8; nf++) {
        *(__half2*)(d0 + nf * 8) = __floats2half2_rn(oa[nf][0] * i0, oa[nf][1] * i0);
        *(__half2*)(d1 + nf * 8) = __floats2half2_rn(oa[nf][2] * i1, oa[nf][3] * i1);
    }
}

// ---------------------------------------------------------------------------
extern "C" void kernel_launch(void* const* d_in, const int* in_sizes, int n_in,
                              void* d_out, int out_size) {
    const float* x    = (const float*)d_in[0];
    const float* cosb = (const float*)d_in[1];
    const float* sinb = (const float*)d_in[2];
    const float* Wq = (const float*)d_in[4];
    const float* Wk = (const float*)d_in[5];
    const float* Wv = (const float*)d_in[6];
    const float* Wo = (const float*)d_in[7];
    const float* qw = (const float*)d_in[8];
    const float* kw = (const float*)d_in[9];
    float* out = (float*)d_out;

    __half *xH, *wqkvH, *woH, *attnH;
    cudaGetSymbolAddress((void**)&xH,    g_xH);
    cudaGetSymbolAddress((void**)&wqkvH, g_wqkvH);
    cudaGetSymbolAddress((void**)&woH,   g_woH);
    cudaGetSymbolAddress((void**)&attnH, g_attnH);

    cudaFuncSetAttribute(gemm_qkv_fused, cudaFuncAttributeMaxDynamicSharedMemorySize, GSM_TOTAL);
    cudaFuncSetAttribute(gemm_f16, cudaFuncAttributeMaxDynamicSharedMemorySize, GSM_TOTAL);
    cudaFuncSetAttribute(flash_mma_kernel, cudaFuncAttributeMaxDynamicSharedMemorySize, FSM_TOTAL);

    // fp16 packs
    cvt_f2h_kernel<<<(MROWS * HID) / 2048, 256>>>(x, xH, MROWS * HID);
    cvt_qkv_kernel<<<(NQKV * HID) / 2048, 256>>>(Wq, Wk, Wv, wqkvH);
    cvt_f2h_kernel<<<(HID * QDIM) / 2048, 256>>>(Wo, woH, HID * QDIM);

    // Fused QKV projection + RMSNorm + RoPE + transpose
    gemm_qkv_fused<<<dim3(NQKV / 128, MROWS / 128), 256, GSM_TOTAL>>>(
        xH, wqkvH, cosb, sinb, qw, kw);

    // fp16 tensorized causal flash attention (2 CTAs/SM)
    flash_mma_kernel<<<dim3(Ss / 64, NH, Bb), 256, FSM_TOTAL>>>();

    // Output projection
    gemm_f16<<<dim3(HID / 128, MROWS / 128), 256, GSM_TOTAL>>>(attnH, woH, out, MROWS, HID, QDIM);
}

// round 17
// speedup vs baseline: 1.1248x; 1.0485x over previous
#include <cuda_runtime.h>
#include <cuda_fp16.h>
#include <cstdint>

// Problem constants
#define Bb   2
#define Ss   2048
#define HID  1024
#define NH   16
#define NKV  8
#define HD   128
#define MROWS (Bb*Ss)          // 4096
#define QDIM (NH*HD)           // 2048
#define KDIM (NKV*HD)          // 1024
#define NQKV (QDIM + 2*KDIM)   // 4096 combined
#define SCALE 0.08838834764831845f

// ---------------------------------------------------------------------------
// Scratch (static device memory; no allocation APIs)
// ---------------------------------------------------------------------------
__device__ __half g_qTh[(size_t)Bb * NH * Ss * HD];    // [b][h][s][d], pre-scaled by SCALE
__device__ __half g_kTh[(size_t)Bb * NKV * Ss * HD];   // [b][hk][s][d]
__device__ __half g_vTh[(size_t)Bb * NKV * Ss * HD];   // [b][hk][d][s] transposed
__device__ __half g_attnH[(size_t)MROWS * QDIM];       // flash output (half)
__device__ __half g_xH[(size_t)MROWS * HID];
__device__ __half g_wqkvH[(size_t)NQKV * HID];         // [Wq;Wk;Wv] rows
__device__ __half g_woH[(size_t)HID * QDIM];

__device__ __forceinline__ uint32_t s2u(const void* p) {
    uint32_t a;
    asm("{ .reg .u64 t; cvta.to.shared.u64 t, %1; cvt.u32.u64 %0, t; }" : "=r"(a) : "l"(p));
    return a;
}
__device__ __forceinline__ void cpasync16(uint32_t dst, const void* src) {
    asm volatile("cp.async.cg.shared.global [%0], [%1], 16;" :: "r"(dst), "l"(src));
}
__device__ __forceinline__ void mma_f16(float* c, const uint32_t* a, const uint32_t* b) {
    asm volatile(
        "mma.sync.aligned.m16n8k16.row.col.f32.f16.f16.f32 "
        "{%0,%1,%2,%3}, {%4,%5,%6,%7}, {%8,%9}, {%0,%1,%2,%3};"
        : "+f"(c[0]), "+f"(c[1]), "+f"(c[2]), "+f"(c[3])
        : "r"(a[0]), "r"(a[1]), "r"(a[2]), "r"(a[3]), "r"(b[0]), "r"(b[1]));
}
__device__ __forceinline__ void ldmx4(uint32_t* r, uint32_t addr) {
    asm volatile("ldmatrix.sync.aligned.m8n8.x4.shared.b16 {%0,%1,%2,%3}, [%4];"
        : "=r"(r[0]), "=r"(r[1]), "=r"(r[2]), "=r"(r[3]) : "r"(addr));
}

// ---------------------------------------------------------------------------
// float -> half packs
// ---------------------------------------------------------------------------
__global__ __launch_bounds__(256) void cvt_f2h_kernel(const float* __restrict__ src,
                                                      __half* __restrict__ dst, int n) {
    int i = (blockIdx.x * 256 + threadIdx.x) * 8;
    if (i < n) {
        float4 v0 = *(const float4*)(src + i);
        float4 v1 = *(const float4*)(src + i + 4);
        __half2* d = (__half2*)(dst + i);
        d[0] = __floats2half2_rn(v0.x, v0.y);
        d[1] = __floats2half2_rn(v0.z, v0.w);
        d[2] = __floats2half2_rn(v1.x, v1.y);
        d[3] = __floats2half2_rn(v1.z, v1.w);
    }
}

__global__ __launch_bounds__(256) void cvt_qkv_kernel(const float* __restrict__ wq,
                                                      const float* __restrict__ wk,
                                                      const float* __restrict__ wv,
                                                      __half* __restrict__ dst) {
    int i = (blockIdx.x * 256 + threadIdx.x) * 8;
    const float* src;
    int off;
    if (i < QDIM * HID)               { src = wq; off = i; }
    else if (i < (QDIM + KDIM) * HID) { src = wk; off = i - QDIM * HID; }
    else                              { src = wv; off = i - (QDIM + KDIM) * HID; }
    float4 v0 = *(const float4*)(src + off);
    float4 v1 = *(const float4*)(src + off + 4);
    __half2* d = (__half2*)(dst + i);
    d[0] = __floats2half2_rn(v0.x, v0.y);
    d[1] = __floats2half2_rn(v0.z, v0.w);
    d[2] = __floats2half2_rn(v1.x, v1.y);
    d[3] = __floats2half2_rn(v1.z, v1.w);
}

// ---------------------------------------------------------------------------
// Shared GEMM mainloop (R7 known-good): BM=128, BN=128, BK=64, 256 threads
// (8 warps 4x2), warp tile 32x64. Double-buffered cp.async, ldmatrix frags.
// ---------------------------------------------------------------------------
#define GPADH 72
#define TILE_H (128 * GPADH)                // 9216 halves per operand tile
#define GSM_TOTAL (4 * TILE_H * 2)          // 73728 B: [A0][A1][B0][B1]

__device__ __forceinline__ void gemm_mainloop(const __half* __restrict__ A,
                                              const __half* __restrict__ B,
                                              __half* As, __half* Bs,
                                              int r0, int c0, int K,
                                              int tid, int wm, int wn,
                                              float acc[2][8][4]) {
#pragma unroll
    for (int mi = 0; mi < 2; mi++)
#pragma unroll
        for (int ni = 0; ni < 8; ni++)
#pragma unroll
            for (int j = 0; j < 4; j++) acc[mi][ni][j] = 0.f;

    const int lane = tid & 31;
    const int l7  = lane & 7;
    const int l8  = (lane >> 3) & 1;
    const int l16 = lane >> 4;

    const uint32_t aoff = (uint32_t)(((wm + l7 + l8 * 8) * GPADH + l16 * 8) * 2);
    const uint32_t boff = (uint32_t)(((wn + l7 + l16 * 8) * GPADH + l8 * 8) * 2);
    const uint32_t asu = s2u(As);
    const uint32_t bsu = s2u(Bs);

    const int T = K >> 6;

    auto load_tile = [&](int t, int s) {
        __half* Ad = As + s * TILE_H;
        __half* Bd = Bs + s * TILE_H;
        const __half* Ap = A + (size_t)r0 * K + t * 64;
        const __half* Bp = B + (size_t)c0 * K + t * 64;
#pragma unroll
        for (int i = 0; i < 4; i++) {
            int ch = tid + i * 256;
            int row = ch >> 3, kc = ch & 7;
            cpasync16(s2u(Ad + row * GPADH + kc * 8), Ap + (size_t)row * K + kc * 8);
            cpasync16(s2u(Bd + row * GPADH + kc * 8), Bp + (size_t)row * K + kc * 8);
        }
        asm volatile("cp.async.commit_group;" ::: "memory");
    };

    load_tile(0, 0);

    for (int t = 0; t < T; t++) {
        int s = t & 1;
        if (t + 1 < T) load_tile(t + 1, s ^ 1);
        if (t + 1 < T) asm volatile("cp.async.wait_group 1;" ::: "memory");
        else           asm volatile("cp.async.wait_group 0;" ::: "memory");
        __syncthreads();

        const uint32_t af = asu + (uint32_t)(s * TILE_H * 2) + aoff;
        const uint32_t bf = bsu + (uint32_t)(s * TILE_H * 2) + boff;
#pragma unroll
        for (int kk = 0; kk < 4; kk++) {
            uint32_t a[2][4], b[8][2];
            ldmx4(a[0], af + kk * 32);
            ldmx4(a[1], af + 16 * GPADH * 2 + kk * 32);
#pragma unroll
            for (int j = 0; j < 4; j++) {
                uint32_t tmp[4];
                ldmx4(tmp, bf + j * 16 * GPADH * 2 + kk * 32);
                b[2 * j][0]     = tmp[0];
                b[2 * j][1]     = tmp[1];
                b[2 * j + 1][0] = tmp[2];
                b[2 * j + 1][1] = tmp[3];
            }
#pragma unroll
            for (int mi = 0; mi < 2; mi++)
#pragma unroll
                for (int ni = 0; ni < 8; ni++)
                    mma_f16(acc[mi][ni], a[mi], b[ni]);
        }
        __syncthreads();
    }
}

// ---------------------------------------------------------------------------
// Fused QKV GEMM + RMSNorm + RoPE + transpose.
// blockIdx.x in [0,16): Q head (pre-scaled by SCALE); [16,24): K; [24,32): V.
// ---------------------------------------------------------------------------
__global__ __launch_bounds__(256, 2) void gemm_qkv_fused(const __half* __restrict__ A,
                                                         const __half* __restrict__ B,
                                                         const float* __restrict__ cosb,
                                                         const float* __restrict__ sinb,
                                                         const float* __restrict__ qw,
                                                         const float* __restrict__ kw) {
    extern __shared__ __half hsm[];
    __half* As = hsm;
    __half* Bs = hsm + 2 * TILE_H;

    const int tid  = threadIdx.x;
    const int warp = tid >> 5;
    const int lane = tid & 31;
    const int wm = (warp >> 1) * 32;
    const int wn = (warp & 1) * 64;
    const int fr = lane >> 2;
    const int fc = lane & 3;

    const int head = blockIdx.x;
    const int r0 = blockIdx.y * 128;

    float acc[2][8][4];
    gemm_mainloop(A, B, As, Bs, r0, head * 128, HID, tid, wm, wn, acc);

    float* S = (float*)hsm;
#pragma unroll
    for (int mi = 0; mi < 2; mi++) {
        int row = wm + mi * 16 + fr;
#pragma unroll
        for (int ni = 0; ni < 8; ni++) {
            int col = wn + ni * 8 + 2 * fc;
            *(float2*)&S[row * 132 + col]       = make_float2(acc[mi][ni][0], acc[mi][ni][1]);
            *(float2*)&S[(row + 8) * 132 + col] = make_float2(acc[mi][ni][2], acc[mi][ni][3]);
        }
    }
    __syncthreads();

    if (head < 24) {
        const bool isQ = (head < 16);
        const float* w = isQ ? qw : kw;
        const float postscale = isQ ? SCALE : 1.0f;   // fold attention scale into Q
        __half* base = isQ
            ? g_qTh + (size_t)head * Ss * HD
            : g_kTh + (size_t)(head - 16) * Ss * HD;
        int nheads = isQ ? NH : NKV;
#pragma unroll 1
        for (int it = 0; it < 16; it++) {
            int row = it * 8 + warp;
            int glob = r0 + row;
            int b = glob >> 11, s = glob & 2047;
            float x0 = S[row * 132 + lane];
            float x1 = S[row * 132 + lane + 32];
            float x2 = S[row * 132 + lane + 64];
            float x3 = S[row * 132 + lane + 96];
            float ssq = x0 * x0 + x1 * x1 + x2 * x2 + x3 * x3;
#pragma unroll
            for (int o = 16; o; o >>= 1) ssq += __shfl_xor_sync(0xffffffffu, ssq, o);
            float inv = rsqrtf(ssq * (1.0f / 128.0f) + 1e-6f) * postscale;
            x0 = x0 * inv * w[lane];
            x1 = x1 * inv * w[lane + 32];
            x2 = x2 * inv * w[lane + 64];
            x3 = x3 * inv * w[lane + 96];
            const float* cp = cosb + (size_t)glob * HD;
            const float* sp = sinb + (size_t)glob * HD;
            float c0 = cp[lane], c1 = cp[lane + 32], c2 = cp[lane + 64], c3 = cp[lane + 96];
            float s0 = sp[lane], s1 = sp[lane + 32], s2 = sp[lane + 64], s3 = sp[lane + 96];
            __half* dst = base + ((size_t)b * nheads * Ss + s) * HD;
            dst[lane]      = __float2half_rn(x0 * c0 - x2 * s0);
            dst[lane + 32] = __float2half_rn(x1 * c1 - x3 * s1);
            dst[lane + 64] = __float2half_rn(x2 * c2 + x0 * s2);
            dst[lane + 96] = __float2half_rn(x3 * c3 + x1 * s3);
        }
    } else {
        int h = head - 24;
        int b = r0 >> 11, s0 = r0 & 2047;
        __half* dst = g_vTh + ((size_t)b * NKV + h) * Ss * HD;
#pragma unroll 1
        for (int it = 0; it < 16; it++) {
            int d = it * 8 + warp;
#pragma unroll
            for (int j = 0; j < 4; j++) {
                float v = S[(lane + 32 * j) * 132 + d];
                dst[(size_t)d * Ss + s0 + lane + 32 * j] = __float2half_rn(v);
            }
        }
    }
}

// ---------------------------------------------------------------------------
// O-projection GEMM
// ---------------------------------------------------------------------------
__global__ __launch_bounds__(256, 2) void gemm_f16(const __half* __restrict__ A,
                                                   const __half* __restrict__ B,
                                                   float* __restrict__ C,
                                                   int M, int N, int K) {
    extern __shared__ __half hsm[];
    __half* As = hsm;
    __half* Bs = hsm + 2 * TILE_H;

    const int tid  = threadIdx.x;
    const int warp = tid >> 5;
    const int lid  = tid & 31;
    const int wm = (warp >> 1) * 32;
    const int wn = (warp & 1) * 64;
    const int fr = lid >> 2;
    const int fc = lid & 3;

    const int r0 = blockIdx.y * 128;
    const int c0 = blockIdx.x * 128;

    float acc[2][8][4];
    gemm_mainloop(A, B, As, Bs, r0, c0, K, tid, wm, wn, acc);

#pragma unroll
    for (int mi = 0; mi < 2; mi++) {
        int row = r0 + wm + mi * 16 + fr;
        float* cp0 = C + (size_t)row * N + c0 + wn + fc * 2;
        float* cp1 = C + (size_t)(row + 8) * N + c0 + wn + fc * 2;
#pragma unroll
        for (int ni = 0; ni < 8; ni++) {
            *(float2*)(cp0 + ni * 8) = make_float2(acc[mi][ni][0], acc[mi][ni][1]);
            *(float2*)(cp1 + ni * 8) = make_float2(acc[mi][ni][2], acc[mi][ni][3]);
        }
    }
}

// ---------------------------------------------------------------------------
// fp16 tensorized flash attention, causal, GQA. Register-resident softmax:
// S never round-trips through smem; only per-row partial max/sum (2x64 floats
// each) cross the warp boundary. P written straight from fragments (half2).
// K SINGLE-buffered, V double-buffered (R15 proven schedule).
// Half region: Qs[64*136] | Ks[64*136] | Vt[2][128*72] | Ps[64*72]  (80896 B)
// Float region @80896: mred[2][64] | lred[2][64]                    (1024 B)
// Total 82048 B -> 2 CTAs/SM.
// ---------------------------------------------------------------------------
#define FQP 136
#define FVP 72
#define HOFF_KS   (64 * FQP)                 // 8704
#define HOFF_VT   (HOFF_KS + 64 * FQP)       // 17408
#define HOFF_PS   (HOFF_VT + 2 * 128 * FVP)  // 35840
#define FSM_TOTAL (80896 + 1024 + 128)       // 82048 B

__global__ __launch_bounds__(256, 2) void flash_mma_kernel() {
    extern __shared__ char fsm[];
    __half* Qs  = (__half*)fsm;
    __half* Ksb = Qs + HOFF_KS;
    __half* Vtb = Qs + HOFF_VT;
    __half* Ps  = Qs + HOFF_PS;
    float* mred = (float*)(fsm + 80896);     // [2][64]
    float* lred = mred + 128;                // [2][64]

    const int tid  = threadIdx.x;
    const int warp = tid >> 5;
    const int lane = tid & 31;
    const int fr = lane >> 2;
    const int fc = lane & 3;
    const int l7  = lane & 7;
    const int l8  = (lane >> 3) & 1;
    const int l16 = lane >> 4;
    const int wmS = (warp >> 1) * 16;
    const int wnS = (warp & 1) * 32;
    const int wcol = warp & 1;
    const int wmO = wmS;
    const int wnO = (warp & 1) * 64;
    const int r0r = wmS + fr;                // this thread's fragment row 0
    const int r1r = r0r + 8;                 // fragment row 1

    const int q0 = blockIdx.x * 64;
    const int h  = blockIdx.y;
    const int b  = blockIdx.z;
    const int hk = h >> 1;

    const __half* qb  = g_qTh + (((size_t)b * NH + h) * Ss + q0) * HD;
    const __half* kb  = g_kTh + ((size_t)b * NKV + hk) * Ss * HD;
    const __half* vtb = g_vTh + ((size_t)b * NKV + hk) * Ss * HD;

    const uint32_t qsu = s2u(Qs);
    const uint32_t ksu = s2u(Ksb);
    const uint32_t vsu = s2u(Vtb);
    const uint32_t psu = s2u(Ps);
    const uint32_t qoff = (uint32_t)(((wmS + l7 + l8 * 8) * FQP + l16 * 8) * 2);
    const uint32_t koff = (uint32_t)(((wnS + l7 + l16 * 8) * FQP + l8 * 8) * 2);
    const uint32_t poff = (uint32_t)(((wmO + l7 + l8 * 8) * FVP + l16 * 8) * 2);
    const uint32_t voff = (uint32_t)(((wnO + l7 + l16 * 8) * FVP + l8 * 8) * 2);

    float m_old0 = -1e30f, m_old1 = -1e30f;
    float l_old0 = 0.f, l_old1 = 0.f;

    float oa[8][4];
#pragma unroll
    for (int nf = 0; nf < 8; nf++)
#pragma unroll
        for (int j = 0; j < 4; j++) oa[nf][j] = 0.f;

    auto loadQ = [&]() {
#pragma unroll
        for (int i = 0; i < 4; i++) {
            int ch = tid + i * 256;
            int row = ch >> 4, kc = ch & 15;
            cpasync16(s2u(Qs + row * FQP + kc * 8), qb + (size_t)row * HD + kc * 8);
        }
    };
    auto loadK = [&](int j) {              // single buffer
        const __half* src = kb + (size_t)(j * 64) * HD;
#pragma unroll
        for (int i = 0; i < 4; i++) {
            int ch = tid + i * 256;
            int row = ch >> 4, kc = ch & 15;
            cpasync16(s2u(Ksb + row * FQP + kc * 8), src + (size_t)row * HD + kc * 8);
        }
    };
    auto loadV = [&](int j, int s) {       // double buffer
        __half* Vd = Vtb + s * 128 * FVP;
#pragma unroll
        for (int i = 0; i < 4; i++) {
            int ch = tid + i * 256;
            int row = ch >> 3, kc = ch & 7;
            cpasync16(s2u(Vd + row * FVP + kc * 8), vtb + (size_t)row * Ss + j * 64 + kc * 8);
        }
    };

    const int nt = blockIdx.x + 1;
    loadQ(); loadK(0); loadV(0, 0);
    asm volatile("cp.async.commit_group;" ::: "memory");

    for (int j = 0; j < nt; j++) {
        asm volatile("cp.async.wait_group 0;" ::: "memory");
        __syncthreads();                     // (A) K(j)/V(j) visible

        // ---- S = Q K^T (Q pre-scaled by SCALE) ----
        float sa[4][4];
#pragma unroll
        for (int nf = 0; nf < 4; nf++)
#pragma unroll
            for (int t = 0; t < 4; t++) sa[nf][t] = 0.f;
#pragma unroll
        for (int kk = 0; kk < 8; kk++) {
            uint32_t a[4], bfr[4][2];
            ldmx4(a, qsu + qoff + kk * 32);
#pragma unroll
            for (int jj = 0; jj < 2; jj++) {
                uint32_t tmp[4];
                ldmx4(tmp, ksu + koff + jj * 16 * FQP * 2 + kk * 32);
                bfr[2 * jj][0]     = tmp[0];
                bfr[2 * jj][1]     = tmp[1];
                bfr[2 * jj + 1][0] = tmp[2];
                bfr[2 * jj + 1][1] = tmp[3];
            }
#pragma unroll
            for (int nf = 0; nf < 4; nf++) mma_f16(sa[nf], a, bfr[nf]);
        }

        // ---- mask (diagonal tile only) + per-row partial max ----
        if (j == nt - 1) {
#pragma unroll
            for (int nf = 0; nf < 4; nf++) {
                int c = j * 64 + wnS + nf * 8 + 2 * fc;
                if (c     > q0 + r0r) sa[nf][0] = -1e9f;
                if (c + 1 > q0 + r0r) sa[nf][1] = -1e9f;
                if (c     > q0 + r1r) sa[nf][2] = -1e9f;
                if (c + 1 > q0 + r1r) sa[nf][3] = -1e9f;
            }
        }
        float pm0 = -1e30f, pm1 = -1e30f;
#pragma unroll
        for (int nf = 0; nf < 4; nf++) {
            pm0 = fmaxf(pm0, fmaxf(sa[nf][0], sa[nf][1]));
            pm1 = fmaxf(pm1, fmaxf(sa[nf][2], sa[nf][3]));
        }
        pm0 = fmaxf(pm0, __shfl_xor_sync(0xffffffffu, pm0, 1));
        pm0 = fmaxf(pm0, __shfl_xor_sync(0xffffffffu, pm0, 2));
        pm1 = fmaxf(pm1, __shfl_xor_sync(0xffffffffu, pm1, 1));
        pm1 = fmaxf(pm1, __shfl_xor_sync(0xffffffffu, pm1, 2));
        if (fc == 0) {
            mred[wcol * 64 + r0r] = pm0;
            mred[wcol * 64 + r1r] = pm1;
        }
        __syncthreads();                     // (B) S reads of Ks done; mred visible

        // Prefetch next K/V (Ks safe to overwrite now)
        if (j + 1 < nt) {
            loadK(j + 1);
            loadV(j + 1, (j + 1) & 1);
            asm volatile("cp.async.commit_group;" ::: "memory");
        }

        // ---- softmax in registers ----
        float mn0 = fmaxf(m_old0, fmaxf(mred[r0r], mred[64 + r0r]));
        float mn1 = fmaxf(m_old1, fmaxf(mred[r1r], mred[64 + r1r]));
        float cr0 = __expf(m_old0 - mn0);
        float cr1 = __expf(m_old1 - mn1);
        float ps0 = 0.f, ps1 = 0.f;
#pragma unroll
        for (int nf = 0; nf < 4; nf++) {
            float p00 = __expf(sa[nf][0] - mn0);
            float p01 = __expf(sa[nf][1] - mn0);
            float p10 = __expf(sa[nf][2] - mn1);
            float p11 = __expf(sa[nf][3] - mn1);
            ps0 += p00 + p01;
            ps1 += p10 + p11;
            int col = wnS + nf * 8 + 2 * fc;
            *(__half2*)&Ps[r0r * FVP + col] = __floats2half2_rn(p00, p01);
            *(__half2*)&Ps[r1r * FVP + col] = __floats2half2_rn(p10, p11);
        }
        ps0 += __shfl_xor_sync(0xffffffffu, ps0, 1);
        ps0 += __shfl_xor_sync(0xffffffffu, ps0, 2);
        ps1 += __shfl_xor_sync(0xffffffffu, ps1, 1);
        ps1 += __shfl_xor_sync(0xffffffffu, ps1, 2);
        if (fc == 0) {
            lred[wcol * 64 + r0r] = ps0;
            lred[wcol * 64 + r1r] = ps1;
        }
        m_old0 = mn0; m_old1 = mn1;
        __syncthreads();                     // (C) Ps + lred visible

        l_old0 = l_old0 * cr0 + lred[r0r] + lred[64 + r0r];
        l_old1 = l_old1 * cr1 + lred[r1r] + lred[64 + r1r];

        // ---- O = O*corr + P V ----
        const uint32_t vf = vsu + (uint32_t)((j & 1) * 128 * FVP * 2) + voff;
#pragma unroll
        for (int nf = 0; nf < 8; nf++) {
            oa[nf][0] *= cr0; oa[nf][1] *= cr0;
            oa[nf][2] *= cr1; oa[nf][3] *= cr1;
        }
#pragma unroll
        for (int kk = 0; kk < 4; kk++) {
            uint32_t a[4], bfr[8][2];
            ldmx4(a, psu + poff + kk * 32);
#pragma unroll
            for (int jj = 0; jj < 4; jj++) {
                uint32_t tmp[4];
                ldmx4(tmp, vf + jj * 16 * FVP * 2 + kk * 32);
                bfr[2 * jj][0]     = tmp[0];
                bfr[2 * jj][1]     = tmp[1];
                bfr[2 * jj + 1][0] = tmp[2];
                bfr[2 * jj + 1][1] = tmp[3];
            }
#pragma unroll
            for (int nf = 0; nf < 8; nf++) mma_f16(oa[nf], a, bfr[nf]);
        }
    }

    // ---- epilogue: rows r0r/r1r are this thread's own softmax rows ----
    float i0 = 1.0f / l_old0;
    float i1 = 1.0f / l_old1;
    int row0 = q0 + wmO + fr;
    __half* d0 = g_attnH + ((size_t)(b * Ss + row0) * NH + h) * HD + wnO + 2 * fc;
    __half* d1 = g_attnH + ((size_t)(b * Ss + row0 + 8) * NH + h) * HD + wnO + 2 * fc;
#pragma unroll
    for (int nf = 0; nf < 8; nf++) {
        *(__half2*)(d0 + nf * 8) = __floats2half2_rn(oa[nf][0] * i0, oa[nf][1] * i0);
        *(__half2*)(d1 + nf * 8) = __floats2half2_rn(oa[nf][2] * i1, oa[nf][3] * i1);
    }
}

// ---------------------------------------------------------------------------
extern "C" void kernel_launch(void* const* d_in, const int* in_sizes, int n_in,
                              void* d_out, int out_size) {
    const float* x    = (const float*)d_in[0];
    const float* cosb = (const float*)d_in[1];
    const float* sinb = (const float*)d_in[2];
    const float* Wq = (const float*)d_in[4];
    const float* Wk = (const float*)d_in[5];
    const float* Wv = (const float*)d_in[6];
    const float* Wo = (const float*)d_in[7];
    const float* qw = (const float*)d_in[8];
    const float* kw = (const float*)d_in[9];
    float* out = (float*)d_out;

    __half *xH, *wqkvH, *woH, *attnH;
    cudaGetSymbolAddress((void**)&xH,    g_xH);
    cudaGetSymbolAddress((void**)&wqkvH, g_wqkvH);
    cudaGetSymbolAddress((void**)&woH,   g_woH);
    cudaGetSymbolAddress((void**)&attnH, g_attnH);

    cudaFuncSetAttribute(gemm_qkv_fused, cudaFuncAttributeMaxDynamicSharedMemorySize, GSM_TOTAL);
    cudaFuncSetAttribute(gemm_f16, cudaFuncAttributeMaxDynamicSharedMemorySize, GSM_TOTAL);
    cudaFuncSetAttribute(flash_mma_kernel, cudaFuncAttributeMaxDynamicSharedMemorySize, FSM_TOTAL);

    // fp16 packs
    cvt_f2h_kernel<<<(MROWS * HID) / 2048, 256>>>(x, xH, MROWS * HID);
    cvt_qkv_kernel<<<(NQKV * HID) / 2048, 256>>>(Wq, Wk, Wv, wqkvH);
    cvt_f2h_kernel<<<(HID * QDIM) / 2048, 256>>>(Wo, woH, HID * QDIM);

    // Fused QKV projection + RMSNorm + RoPE + transpose (Q pre-scaled)
    gemm_qkv_fused<<<dim3(NQKV / 128, MROWS / 128), 256, GSM_TOTAL>>>(
        xH, wqkvH, cosb, sinb, qw, kw);

    // fp16 tensorized causal flash attention (2 CTAs/SM, register softmax)
    flash_mma_kernel<<<dim3(Ss / 64, NH, Bb), 256, FSM_TOTAL>>>();

    // Output projection
    gemm_f16<<<dim3(HID / 128, MROWS / 128), 256, GSM_TOTAL>>>(attnH, woH, out, MROWS, HID, QDIM);
}